// round 3
// baseline (speedup 1.0000x reference)
#include <cuda_runtime.h>
#include <cstdint>

#define Nn  50000
#define NTt 300000
#define RPk 16
#define Ee  32
#define Cc  32

// ------------------------- device scratch (static, no allocs) -------------
__device__ float g_lat1[(size_t)NTt * RPk];        // 19.2 MB
__device__ float g_lat2[(size_t)NTt * RPk];        // 19.2 MB
__device__ float g_colsum[Nn * RPk];               // 3.2 MB
__device__ float g_rowsum[Nn * RPk];               // 3.2 MB
__device__ float g_h[Nn * Ee];                     // 6.4 MB
__device__ float g_h2[(size_t)RPk * Nn * Ee];      // 102.4 MB
__device__ int   g_deg_s[Nn];
__device__ int   g_deg_o[Nn];
__device__ int   g_off_s[Nn];
__device__ int   g_off_o[Nn];
__device__ int   g_cur_s[Nn];
__device__ int   g_cur_o[Nn];
__device__ int   g_perm_s[NTt];
__device__ int   g_perm_o[NTt];
__device__ int   g_counter[2];

// ------------------------- small helpers ----------------------------------
union F4U { float4 f; unsigned long long u[2]; float s[4]; };

__device__ __forceinline__ unsigned long long splat2(float v) {
    unsigned long long r;
    asm("mov.b64 %0, {%1, %1};" : "=l"(r) : "f"(v));
    return r;
}
__device__ __forceinline__ unsigned long long ffma2(unsigned long long a,
                                                    unsigned long long b,
                                                    unsigned long long c) {
    unsigned long long d;
    asm("fma.rn.f32x2 %0, %1, %2, %3;" : "=l"(d) : "l"(a), "l"(b), "l"(c));
    return d;
}
__device__ __forceinline__ void red4(float4* a, float4 v) {
    asm volatile("red.global.add.v4.f32 [%0], {%1, %2, %3, %4};"
                 :: "l"(a), "f"(v.x), "f"(v.y), "f"(v.z), "f"(v.w) : "memory");
}
__device__ __forceinline__ void red1(float* a, float v) {
    asm volatile("red.global.add.f32 [%0], %1;" :: "l"(a), "f"(v) : "memory");
}

// ------------------------- init: zero scratch -----------------------------
__global__ void k_init() {
    size_t i = (size_t)blockIdx.x * blockDim.x + threadIdx.x;
    size_t stride = (size_t)gridDim.x * blockDim.x;
    float4 z = make_float4(0.f, 0.f, 0.f, 0.f);
    for (size_t p = i; p < (size_t)RPk * Nn * Ee / 4; p += stride)
        ((float4*)g_h2)[p] = z;
    for (size_t p = i; p < (size_t)Nn * RPk / 4; p += stride) {
        ((float4*)g_colsum)[p] = z;
        ((float4*)g_rowsum)[p] = z;
    }
    for (size_t p = i; p < (size_t)Nn * Ee / 4; p += stride)
        ((float4*)g_h)[p] = z;
    for (size_t p = i; p < Nn / 4; p += stride) {
        ((int4*)g_deg_s)[p] = make_int4(0, 0, 0, 0);
        ((int4*)g_deg_o)[p] = make_int4(0, 0, 0, 0);
    }
    if (i == 0) { g_counter[0] = 0; g_counter[1] = 0; }
}

// ------------------------- degree count -----------------------------------
__global__ void k_deg(const int* __restrict__ s_idx, const int* __restrict__ o_idx) {
    int t = blockIdx.x * blockDim.x + threadIdx.x;
    if (t < NTt) {
        atomicAdd(&g_deg_s[s_idx[t]], 1);
        atomicAdd(&g_deg_o[o_idx[t]], 1);
    }
}

// ---------------- CSR range allocation (warp-aggregated, unordered) -------
__global__ void k_alloc() {
    int i = blockIdx.x * blockDim.x + threadIdx.x;
    int lane = threadIdx.x & 31;
    int ds = (i < Nn) ? g_deg_s[i] : 0;
    int dq = (i < Nn) ? g_deg_o[i] : 0;
    int ss = ds, so = dq;
#pragma unroll
    for (int off = 1; off < 32; off <<= 1) {
        int a = __shfl_up_sync(0xffffffffu, ss, off);
        int b = __shfl_up_sync(0xffffffffu, so, off);
        if (lane >= off) { ss += a; so += b; }
    }
    int bs = 0, bo = 0;
    if (lane == 31) {
        bs = atomicAdd(&g_counter[0], ss);
        bo = atomicAdd(&g_counter[1], so);
    }
    bs = __shfl_sync(0xffffffffu, bs, 31);
    bo = __shfl_sync(0xffffffffu, bo, 31);
    if (i < Nn) {
        int es = bs + ss - ds;
        int eo = bo + so - dq;
        g_off_s[i] = es; g_cur_s[i] = es;
        g_off_o[i] = eo; g_cur_o[i] = eo;
    }
}

// ------------------------- per-edge MLPs (2 edges / thread) ---------------
__device__ __forceinline__ void mlp16x2(const float* __restrict__ nha,
                                        const float* __restrict__ nhb,
                                        const float* __restrict__ Wa,
                                        const float* __restrict__ ba,
                                        const float* __restrict__ Wb,
                                        const float* __restrict__ bb,
                                        float* __restrict__ la,
                                        float* __restrict__ lb) {
    unsigned long long hA[32], hB[32];
#pragma unroll
    for (int j = 0; j < 32; j++) { hA[j] = ((const unsigned long long*)ba)[j]; hB[j] = hA[j]; }
#pragma unroll 1
    for (int i4 = 0; i4 < 16; i4++) {
        float4 va = __ldg((const float4*)nha + i4);
        float4 vb = __ldg((const float4*)nhb + i4);
        float xa[4] = { va.x, va.y, va.z, va.w };
        float xb[4] = { vb.x, vb.y, vb.z, vb.w };
#pragma unroll
        for (int u = 0; u < 4; u++) {
            unsigned long long sa = splat2(xa[u]);
            unsigned long long sb = splat2(xb[u]);
            const float4* wr = (const float4*)(Wa + (i4 * 4 + u) * 64);
#pragma unroll
            for (int j4 = 0; j4 < 16; j4++) {
                F4U w; w.f = wr[j4];                     // one LDS.128 feeds 4 ffma2
                hA[2 * j4]     = ffma2(sa, w.u[0], hA[2 * j4]);
                hA[2 * j4 + 1] = ffma2(sa, w.u[1], hA[2 * j4 + 1]);
                hB[2 * j4]     = ffma2(sb, w.u[0], hB[2 * j4]);
                hB[2 * j4 + 1] = ffma2(sb, w.u[1], hB[2 * j4 + 1]);
            }
        }
    }
    unsigned long long aA[8], aB[8];
#pragma unroll
    for (int k = 0; k < 8; k++) { aA[k] = ((const unsigned long long*)bb)[k]; aB[k] = aA[k]; }
#pragma unroll 1
    for (int j = 0; j < 32; j++) {
        float2 ha = *(float2*)&hA[j];
        float2 hb = *(float2*)&hB[j];
        unsigned long long a0 = splat2(fmaxf(ha.x, 0.f));
        unsigned long long a1 = splat2(fmaxf(ha.y, 0.f));
        unsigned long long b0 = splat2(fmaxf(hb.x, 0.f));
        unsigned long long b1 = splat2(fmaxf(hb.y, 0.f));
        const float4* w0 = (const float4*)(Wb + (2 * j) * 16);
        const float4* w1 = (const float4*)(Wb + (2 * j + 1) * 16);
#pragma unroll
        for (int q = 0; q < 4; q++) {
            F4U wq0; wq0.f = w0[q];
            F4U wq1; wq1.f = w1[q];
            aA[2 * q]     = ffma2(a1, wq1.u[0], ffma2(a0, wq0.u[0], aA[2 * q]));
            aA[2 * q + 1] = ffma2(a1, wq1.u[1], ffma2(a0, wq0.u[1], aA[2 * q + 1]));
            aB[2 * q]     = ffma2(b1, wq1.u[0], ffma2(b0, wq0.u[0], aB[2 * q]));
            aB[2 * q + 1] = ffma2(b1, wq1.u[1], ffma2(b0, wq0.u[1], aB[2 * q + 1]));
        }
    }
#pragma unroll
    for (int k = 0; k < 8; k++) {
        float2 va = *(float2*)&aA[k];
        float2 vb = *(float2*)&aB[k];
        la[2 * k] = va.x; la[2 * k + 1] = va.y;
        lb[2 * k] = vb.x; lb[2 * k + 1] = vb.y;
    }
}

__device__ __forceinline__ void softmax16(float* l) {
    float m = l[0];
#pragma unroll
    for (int k = 1; k < 16; k++) m = fmaxf(m, l[k]);
    float s = 0.f;
#pragma unroll
    for (int k = 0; k < 16; k++) { l[k] = __expf(l[k] - m); s += l[k]; }
    float inv = 1.f / s;
#pragma unroll
    for (int k = 0; k < 16; k++) l[k] *= inv;
}

__global__ void __launch_bounds__(256)
k_mlp(const int* __restrict__ s_idx, const int* __restrict__ o_idx,
      const float* __restrict__ nhots,
      const float* __restrict__ W1a, const float* __restrict__ b1a,
      const float* __restrict__ W1b, const float* __restrict__ b1b,
      const float* __restrict__ W2a, const float* __restrict__ b2a,
      const float* __restrict__ W2b, const float* __restrict__ b2b) {
    __shared__ __align__(16) float sW1a[64 * 64];
    __shared__ __align__(16) float sW1b[64 * 16];
    __shared__ __align__(16) float sW2a[64 * 64];
    __shared__ __align__(16) float sW2b[64 * 16];
    __shared__ __align__(16) float sb1a[64], sb2a[64];
    __shared__ __align__(16) float sb1b[16], sb2b[16];
    __shared__ float swr1[8], swr2[8];

    int tid = threadIdx.x;
    for (int i = tid; i < 64 * 64; i += 256) { sW1a[i] = W1a[i]; sW2a[i] = W2a[i]; }
    for (int i = tid; i < 64 * 16; i += 256) { sW1b[i] = W1b[i]; sW2b[i] = W2b[i]; }
    if (tid < 64) { sb1a[tid] = b1a[tid]; sb2a[tid] = b2a[tid]; }
    if (tid < 16) { sb1b[tid] = b1b[tid]; sb2b[tid] = b2b[tid]; }
    __syncthreads();

    int pair = blockIdx.x * 256 + tid;
    int t0 = pair * 2, t1 = t0 + 1;      // NTt is even
    float r1 = 0.f, r2 = 0.f;
    if (t0 < NTt) {
        const float* nha = nhots + (size_t)t0 * 64;
        const float* nhb = nhots + (size_t)t1 * 64;
        int s0 = s_idx[t0], o0 = o_idx[t0];
        int s1 = s_idx[t1], o1 = o_idx[t1];

        {
            float l1a[16], l1b[16];
            mlp16x2(nha, nhb, sW1a, sb1a, sW1b, sb1b, l1a, l1b);
            softmax16(l1a);
            softmax16(l1b);
            float4* pa = (float4*)&g_lat1[(size_t)t0 * 16];
            float4* pb = (float4*)&g_lat1[(size_t)t1 * 16];
#pragma unroll
            for (int q = 0; q < 4; q++) {
                pa[q] = make_float4(l1a[4 * q], l1a[4 * q + 1], l1a[4 * q + 2], l1a[4 * q + 3]);
                pb[q] = make_float4(l1b[4 * q], l1b[4 * q + 1], l1b[4 * q + 2], l1b[4 * q + 3]);
            }
#pragma unroll
            for (int k = 1; k < 16; k++) {
                red1(&g_colsum[o0 * k], l1a[k]);
                red1(&g_colsum[o1 * k], l1b[k]);
            }
            r1 = l1a[0] + l1b[0];
        }
        {
            float l2a[16], l2b[16];
            mlp16x2(nha, nhb, sW2a, sb2a, sW2b, sb2b, l2a, l2b);
            softmax16(l2a);
            softmax16(l2b);
            float4* pa = (float4*)&g_lat2[(size_t)t0 * 16];
            float4* pb = (float4*)&g_lat2[(size_t)t1 * 16];
#pragma unroll
            for (int q = 0; q < 4; q++) {
                pa[q] = make_float4(l2a[4 * q], l2a[4 * q + 1], l2a[4 * q + 2], l2a[4 * q + 3]);
                pb[q] = make_float4(l2b[4 * q], l2b[4 * q + 1], l2b[4 * q + 2], l2b[4 * q + 3]);
            }
#pragma unroll
            for (int k = 1; k < 16; k++) {
                red1(&g_rowsum[s0 * k], l2a[k]);
                red1(&g_rowsum[s1 * k], l2b[k]);
            }
            r2 = l2a[0] + l2b[0];
        }
    }
    // block-reduce the k=0 contributions (all hit bin 0)
#pragma unroll
    for (int off = 16; off; off >>= 1) {
        r1 += __shfl_down_sync(0xffffffffu, r1, off);
        r2 += __shfl_down_sync(0xffffffffu, r2, off);
    }
    int wid = tid >> 5, lane = tid & 31;
    if (lane == 0) { swr1[wid] = r1; swr2[wid] = r2; }
    __syncthreads();
    if (tid == 0) {
        float a = 0.f, b = 0.f;
#pragma unroll
        for (int i = 0; i < 8; i++) { a += swr1[i]; b += swr2[i]; }
        red1(&g_colsum[0], a);
        red1(&g_rowsum[0], b);
    }
}

__global__ void k_scatter(const int* __restrict__ s_idx,
                          const int* __restrict__ o_idx) {
    int t = blockIdx.x * blockDim.x + threadIdx.x;
    if (t < NTt) {
        int s = s_idx[t], o = o_idx[t];
        g_perm_s[atomicAdd(&g_cur_s[s], 1)] = t;
        g_perm_o[atomicAdd(&g_cur_o[o], 1)] = t;
    }
}

// ------ layer-1 spmm, warp per o: weights loaded once, red into h[s] ------
__global__ void __launch_bounds__(256)
k_spmm1(const int* __restrict__ s_idx, const float* __restrict__ w1) {
    int w = (blockIdx.x * blockDim.x + threadIdx.x) >> 5;
    int lane = threadIdx.x & 31;
    if (w >= Nn) return;
    int o = w;
    int deg = g_deg_o[o];
    if (deg == 0) return;
    int beg = g_off_o[o];

    float wk[16];
#pragma unroll
    for (int k = 0; k < 16; k++) {
        int j = o * k;
        float c = g_colsum[j];                 // uniform across warp -> broadcast
        float inv = (c > 0.f) ? __frcp_rn(c) : 0.f;
        wk[k] = w1[(size_t)j * 32 + lane] * inv;
    }

    for (int p = beg; p < beg + deg; p++) {
        int t = g_perm_o[p];
        int s = s_idx[t];
        float lv = (lane < 16) ? g_lat1[(size_t)t * 16 + lane] : 0.f;
        float acc = 0.f;
#pragma unroll
        for (int k = 0; k < 16; k++)
            acc += __shfl_sync(0xffffffffu, lv, k) * wk[k];
        red1(&g_h[s * 32 + lane], acc);
    }
}

// ------------------------- h = relu(h + bias1) -----------------------------
__global__ void k_relu(const float* __restrict__ bias1) {
    int i = blockIdx.x * blockDim.x + threadIdx.x;
    if (i < Nn * Ee)
        g_h[i] = fmaxf(g_h[i] + bias1[i & 31], 0.f);
}

// ------------------------- layer-2 spmm into h2 (warp per s) --------------
__global__ void __launch_bounds__(256)
k_spmm2(const int* __restrict__ o_idx) {
    __shared__ __align__(16) float stage[8][16 * 32];
    int wid = threadIdx.x >> 5, lane = threadIdx.x & 31;
    int s = blockIdx.x * 8 + wid;
    if (s >= Nn) return;
    int deg = g_deg_s[s];
    if (deg == 0) return;
    int beg = g_off_s[s];
    float acc[16];
#pragma unroll
    for (int k = 0; k < 16; k++) acc[k] = 0.f;
    for (int p = beg; p < beg + deg; p++) {
        int t = g_perm_s[p];
        int o = o_idx[t];
        float hv = g_h[o * 32 + lane];
        float lv = (lane < 16) ? g_lat2[(size_t)t * 16 + lane] : 0.f;
#pragma unroll
        for (int k = 0; k < 16; k++)
            acc[k] += __shfl_sync(0xffffffffu, lv, k) * hv;
    }
    float* st = stage[wid];
#pragma unroll
    for (int k = 0; k < 16; k++) st[k * 32 + lane] = acc[k];
    __syncwarp();
#pragma unroll
    for (int it = 0; it < 4; it++) {
        int idx = it * 32 + lane;        // 0..127 over 16 rows x 8 float4
        int k = idx >> 3, q = idx & 7;
        float4 v = ((float4*)st)[idx];
        int j = s * k;
        red4(&((float4*)g_h2)[(size_t)j * 8 + q], v);
    }
}

// ------------------------- einsum + bias2: out[node] ----------------------
__global__ void __launch_bounds__(256)
k_out(const float* __restrict__ w2, const float* __restrict__ bias2,
      float* __restrict__ out) {
    extern __shared__ __align__(16) float sw2[];   // 16*32*32 floats = 64 KB
    for (int i = threadIdx.x; i < 16 * 32 * 32; i += 256) sw2[i] = w2[i];
    __syncthreads();
    int node = blockIdx.x * 256 + threadIdx.x;
    if (node >= Nn) return;
    unsigned long long acc2[16];
#pragma unroll
    for (int c2 = 0; c2 < 16; c2++)
        acc2[c2] = ((const unsigned long long*)bias2)[c2];
#pragma unroll 1
    for (int r = 0; r < 16; r++) {
        int j = r * Nn + node;
        float rs = g_rowsum[j];
        float inv = (rs > 0.f) ? __frcp_rn(rs) : 0.f;
        const float4* hrow = (const float4*)&g_h2[(size_t)j * 32];
#pragma unroll
        for (int e4 = 0; e4 < 8; e4++) {
            float4 hv = hrow[e4];
            float vals[4] = { hv.x * inv, hv.y * inv, hv.z * inv, hv.w * inv };
#pragma unroll
            for (int u = 0; u < 4; u++) {
                int e = e4 * 4 + u;
                unsigned long long xs = splat2(vals[u]);
                const float4* wr4 = (const float4*)&sw2[(r * 32 + e) * 32];
#pragma unroll
                for (int c4 = 0; c4 < 8; c4++) {
                    F4U w; w.f = wr4[c4];               // one LDS.128 feeds 2 ffma2
                    acc2[2 * c4]     = ffma2(xs, w.u[0], acc2[2 * c4]);
                    acc2[2 * c4 + 1] = ffma2(xs, w.u[1], acc2[2 * c4 + 1]);
                }
            }
        }
    }
    unsigned long long* op = (unsigned long long*)(out + (size_t)node * 32);
#pragma unroll
    for (int c2 = 0; c2 < 16; c2++) op[c2] = acc2[c2];
}

// ------------------------- launch -----------------------------------------
extern "C" void kernel_launch(void* const* d_in, const int* in_sizes, int n_in,
                              void* d_out, int out_size) {
    const int*   s_idx = (const int*)d_in[0];
    const int*   o_idx = (const int*)d_in[1];
    const float* nhots = (const float*)d_in[2];
    const float* W1a   = (const float*)d_in[3];
    const float* b1a   = (const float*)d_in[4];
    const float* W1b   = (const float*)d_in[5];
    const float* b1b   = (const float*)d_in[6];
    const float* W2a   = (const float*)d_in[7];
    const float* b2a   = (const float*)d_in[8];
    const float* W2b   = (const float*)d_in[9];
    const float* b2b   = (const float*)d_in[10];
    const float* w1    = (const float*)d_in[11];
    const float* w2    = (const float*)d_in[12];
    const float* bias1 = (const float*)d_in[13];
    const float* bias2 = (const float*)d_in[14];
    float* out = (float*)d_out;

    cudaFuncSetAttribute(k_out, cudaFuncAttributeMaxDynamicSharedMemorySize,
                         16 * 32 * 32 * (int)sizeof(float));

    int npair = NTt / 2;
    k_init<<<2048, 256>>>();                                   // 0
    k_deg<<<(NTt + 255) / 256, 256>>>(s_idx, o_idx);           // 1
    k_alloc<<<(Nn + 255) / 256, 256>>>();                      // 2
    k_mlp<<<(npair + 255) / 256, 256>>>(s_idx, o_idx, nhots,   // 3 <- ncu slot
                                        W1a, b1a, W1b, b1b,
                                        W2a, b2a, W2b, b2b);
    k_scatter<<<(NTt + 255) / 256, 256>>>(s_idx, o_idx);       // 4
    k_spmm1<<<(Nn * 32 + 255) / 256, 256>>>(s_idx, w1);        // 5
    k_relu<<<(Nn * Ee + 255) / 256, 256>>>(bias1);             // 6
    k_spmm2<<<(Nn + 7) / 8, 256>>>(o_idx);                     // 7
    k_out<<<(Nn + 255) / 256, 256, 16 * 32 * 32 * (int)sizeof(float)>>>(w2, bias2, out); // 8
}

// round 4
// speedup vs baseline: 1.3053x; 1.3053x over previous
#include <cuda_runtime.h>
#include <cstdint>

#define Nn  50000
#define NTt 300000
#define RPk 16
#define Ee  32
#define Cc  32

// ------------------------- device scratch (static, no allocs) -------------
__device__ float g_lat1[(size_t)NTt * RPk];        // 19.2 MB
__device__ float g_lat2[(size_t)NTt * RPk];        // 19.2 MB
__device__ float g_colsum[Nn * RPk];               // 3.2 MB
__device__ float g_rowsum[Nn * RPk];               // 3.2 MB
__device__ float g_h[Nn * Ee];                     // 6.4 MB
__device__ float g_h2[(size_t)RPk * Nn * Ee];      // 102.4 MB
__device__ int   g_deg_s[Nn];
__device__ int   g_deg_o[Nn];
__device__ int   g_off_s[Nn];
__device__ int   g_off_o[Nn];
__device__ int   g_cur_s[Nn];
__device__ int   g_cur_o[Nn];
__device__ int   g_perm_s[NTt];
__device__ int   g_perm_o[NTt];
__device__ int   g_counter[2];

// ------------------------- small helpers ----------------------------------
typedef unsigned long long ULL;
union F4U { float4 f; ULL u[2]; float s[4]; };

__device__ __forceinline__ ULL splat2(float v) {
    ULL r;
    asm("mov.b64 %0, {%1, %1};" : "=l"(r) : "f"(v));
    return r;
}
__device__ __forceinline__ ULL ffma2(ULL a, ULL b, ULL c) {
    ULL d;
    asm("fma.rn.f32x2 %0, %1, %2, %3;" : "=l"(d) : "l"(a), "l"(b), "l"(c));
    return d;
}
__device__ __forceinline__ void red4(float4* a, float4 v) {
    asm volatile("red.global.add.v4.f32 [%0], {%1, %2, %3, %4};"
                 :: "l"(a), "f"(v.x), "f"(v.y), "f"(v.z), "f"(v.w) : "memory");
}
__device__ __forceinline__ void red1(float* a, float v) {
    asm volatile("red.global.add.f32 [%0], %1;" :: "l"(a), "f"(v) : "memory");
}

// ------------------------- init: zero scratch -----------------------------
__global__ void k_init() {
    size_t i = (size_t)blockIdx.x * blockDim.x + threadIdx.x;
    size_t stride = (size_t)gridDim.x * blockDim.x;
    float4 z = make_float4(0.f, 0.f, 0.f, 0.f);
    for (size_t p = i; p < (size_t)RPk * Nn * Ee / 4; p += stride)
        ((float4*)g_h2)[p] = z;
    for (size_t p = i; p < (size_t)Nn * RPk / 4; p += stride) {
        ((float4*)g_colsum)[p] = z;
        ((float4*)g_rowsum)[p] = z;
    }
    for (size_t p = i; p < (size_t)Nn * Ee / 4; p += stride)
        ((float4*)g_h)[p] = z;
    for (size_t p = i; p < Nn / 4; p += stride) {
        ((int4*)g_deg_s)[p] = make_int4(0, 0, 0, 0);
        ((int4*)g_deg_o)[p] = make_int4(0, 0, 0, 0);
    }
    if (i == 0) { g_counter[0] = 0; g_counter[1] = 0; }
}

// ------------------------- degree count -----------------------------------
__global__ void k_deg(const int* __restrict__ s_idx, const int* __restrict__ o_idx) {
    int t = blockIdx.x * blockDim.x + threadIdx.x;
    if (t < NTt) {
        atomicAdd(&g_deg_s[s_idx[t]], 1);
        atomicAdd(&g_deg_o[o_idx[t]], 1);
    }
}

// ---------------- CSR range allocation (warp-aggregated, unordered) -------
__global__ void k_alloc() {
    int i = blockIdx.x * blockDim.x + threadIdx.x;
    int lane = threadIdx.x & 31;
    int ds = (i < Nn) ? g_deg_s[i] : 0;
    int dq = (i < Nn) ? g_deg_o[i] : 0;
    int ss = ds, so = dq;
#pragma unroll
    for (int off = 1; off < 32; off <<= 1) {
        int a = __shfl_up_sync(0xffffffffu, ss, off);
        int b = __shfl_up_sync(0xffffffffu, so, off);
        if (lane >= off) { ss += a; so += b; }
    }
    int bs = 0, bo = 0;
    if (lane == 31) {
        bs = atomicAdd(&g_counter[0], ss);
        bo = atomicAdd(&g_counter[1], so);
    }
    bs = __shfl_sync(0xffffffffu, bs, 31);
    bo = __shfl_sync(0xffffffffu, bo, 31);
    if (i < Nn) {
        int es = bs + ss - ds;
        int eo = bo + so - dq;
        g_off_s[i] = es; g_cur_s[i] = es;
        g_off_o[i] = eo; g_cur_o[i] = eo;
    }
}

// ------------- fused block-GEMM MLP + softmax + segment sum ---------------
// block = 128 edges, 256 threads. smem layout (floats):
//   X   [128][65]  @ 0       (8320)   -- reused for lat[128][17] in epilogue
//   H   [128][67]  @ 8320    (8576)
//   W   [64][64]   @ 16896   (4096)
//   Wb  [64][16]   @ 20992   (1024)
//   ba  [64]       @ 22016
//   bb  [16]       @ 22080
//   red [8]        @ 22096
#define SM_X   0
#define SM_H   8320
#define SM_W   16896
#define SM_WB  20992
#define SM_BA  22016
#define SM_BB  22080
#define SM_RED 22096
#define SM_FLOATS 22112

__device__ __forceinline__ void softmax16(float* l) {
    float m = l[0];
#pragma unroll
    for (int k = 1; k < 16; k++) m = fmaxf(m, l[k]);
    float s = 0.f;
#pragma unroll
    for (int k = 0; k < 16; k++) { l[k] = __expf(l[k] - m); s += l[k]; }
    float inv = 1.f / s;
#pragma unroll
    for (int k = 0; k < 16; k++) l[k] *= inv;
}

template<int WHICH>
__global__ void __launch_bounds__(256)
k_mlpg(const int* __restrict__ nidx,          // o_idx (WHICH=1) / s_idx (WHICH=2)
       const float* __restrict__ nhots,
       const float* __restrict__ Wa, const float* __restrict__ ba,
       const float* __restrict__ Wb, const float* __restrict__ bb,
       float* __restrict__ lat_out, float* __restrict__ sum_out) {
    extern __shared__ __align__(16) float sm[];
    int tid = threadIdx.x;
    int e_base = blockIdx.x * 128;

    // ---- stage X [128 edges][64] into sm+SM_X, row pad 65 ----
#pragma unroll
    for (int j = 0; j < 8; j++) {
        int idx4 = tid + 256 * j;            // 0..2047 float4 slots
        int e = idx4 >> 4, kq = idx4 & 15;
        float4 v = make_float4(0.f, 0.f, 0.f, 0.f);
        if (e_base + e < NTt)
            v = __ldg((const float4*)(nhots + (size_t)(e_base + e) * 64) + kq);
        float* dst = sm + SM_X + e * 65 + kq * 4;
        dst[0] = v.x; dst[1] = v.y; dst[2] = v.z; dst[3] = v.w;
    }
    // ---- stage weights ----
    for (int i = tid; i < 4096; i += 256) sm[SM_W + i] = Wa[i];
    for (int i = tid; i < 1024; i += 256) sm[SM_WB + i] = Wb[i];
    if (tid < 64) sm[SM_BA + tid] = ba[tid];
    if (tid < 16) sm[SM_BB + tid] = bb[tid];
    __syncthreads();

    int lane = tid & 31, wq = tid >> 5;

    // ---- phase 1: H[128][64] = relu(X @ Wa + ba); thread: 4 edges x 8 hid --
    {
        int h0 = wq * 8;
        ULL acc[4][4];
        ULL b0 = *(ULL*)&sm[SM_BA + h0];
        ULL b1 = *(ULL*)&sm[SM_BA + h0 + 2];
        ULL b2 = *(ULL*)&sm[SM_BA + h0 + 4];
        ULL b3 = *(ULL*)&sm[SM_BA + h0 + 6];
#pragma unroll
        for (int i = 0; i < 4; i++) {
            acc[i][0] = b0; acc[i][1] = b1; acc[i][2] = b2; acc[i][3] = b3;
        }
#pragma unroll 2
        for (int k = 0; k < 64; k++) {
            float x0 = sm[SM_X + lane * 65 + k];
            float x1 = sm[SM_X + (lane + 32) * 65 + k];
            float x2 = sm[SM_X + (lane + 64) * 65 + k];
            float x3 = sm[SM_X + (lane + 96) * 65 + k];
            F4U wA; wA.f = *(float4*)&sm[SM_W + k * 64 + h0];
            F4U wB; wB.f = *(float4*)&sm[SM_W + k * 64 + h0 + 4];
            ULL s0 = splat2(x0), s1 = splat2(x1), s2 = splat2(x2), s3 = splat2(x3);
            acc[0][0] = ffma2(s0, wA.u[0], acc[0][0]);
            acc[0][1] = ffma2(s0, wA.u[1], acc[0][1]);
            acc[0][2] = ffma2(s0, wB.u[0], acc[0][2]);
            acc[0][3] = ffma2(s0, wB.u[1], acc[0][3]);
            acc[1][0] = ffma2(s1, wA.u[0], acc[1][0]);
            acc[1][1] = ffma2(s1, wA.u[1], acc[1][1]);
            acc[1][2] = ffma2(s1, wB.u[0], acc[1][2]);
            acc[1][3] = ffma2(s1, wB.u[1], acc[1][3]);
            acc[2][0] = ffma2(s2, wA.u[0], acc[2][0]);
            acc[2][1] = ffma2(s2, wA.u[1], acc[2][1]);
            acc[2][2] = ffma2(s2, wB.u[0], acc[2][2]);
            acc[2][3] = ffma2(s2, wB.u[1], acc[2][3]);
            acc[3][0] = ffma2(s3, wA.u[0], acc[3][0]);
            acc[3][1] = ffma2(s3, wA.u[1], acc[3][1]);
            acc[3][2] = ffma2(s3, wB.u[0], acc[3][2]);
            acc[3][3] = ffma2(s3, wB.u[1], acc[3][3]);
        }
        // relu + store H (pad 67, scalar stores: conflict-free, 3*lane pattern)
#pragma unroll
        for (int i = 0; i < 4; i++) {
            float* hr = sm + SM_H + (lane + 32 * i) * 67 + h0;
#pragma unroll
            for (int q = 0; q < 4; q++) {
                float2 v = *(float2*)&acc[i][q];
                hr[2 * q]     = fmaxf(v.x, 0.f);
                hr[2 * q + 1] = fmaxf(v.y, 0.f);
            }
        }
    }
    __syncthreads();

    // ---- phase 2: lat[128][16] = H @ Wb + bb; thread: 4 edges x 2 classes --
    {
        int c0 = wq * 2;
        ULL a2[4];
        ULL binit = *(ULL*)&sm[SM_BB + c0];
#pragma unroll
        for (int i = 0; i < 4; i++) a2[i] = binit;
#pragma unroll 2
        for (int j = 0; j < 64; j++) {
            float h0v = sm[SM_H + lane * 67 + j];
            float h1v = sm[SM_H + (lane + 32) * 67 + j];
            float h2v = sm[SM_H + (lane + 64) * 67 + j];
            float h3v = sm[SM_H + (lane + 96) * 67 + j];
            ULL wb = *(ULL*)&sm[SM_WB + j * 16 + c0];
            a2[0] = ffma2(splat2(h0v), wb, a2[0]);
            a2[1] = ffma2(splat2(h1v), wb, a2[1]);
            a2[2] = ffma2(splat2(h2v), wb, a2[2]);
            a2[3] = ffma2(splat2(h3v), wb, a2[3]);
        }
        __syncthreads();   // everyone done reading H/X before lat overlays X
        // store lat into X region, row pad 17 (conflict-free: 17*lane)
#pragma unroll
        for (int i = 0; i < 4; i++) {
            float2 v = *(float2*)&a2[i];
            float* lr = sm + SM_X + (lane + 32 * i) * 17 + c0;
            lr[0] = v.x; lr[1] = v.y;
        }
    }
    __syncthreads();

    // ---- epilogue: softmax, emit latents, segment-sum atomics ----
    float part = 0.f;
    if (tid < 128 && e_base + tid < NTt) {
        int e = e_base + tid;
        float l[16];
        const float* lr = sm + SM_X + tid * 17;
#pragma unroll
        for (int c = 0; c < 16; c++) l[c] = lr[c];
        softmax16(l);
        float4* po = (float4*)(lat_out + (size_t)e * 16);
#pragma unroll
        for (int q = 0; q < 4; q++)
            po[q] = make_float4(l[4 * q], l[4 * q + 1], l[4 * q + 2], l[4 * q + 3]);
        int ix = nidx[e];
#pragma unroll
        for (int k = 1; k < 16; k++)
            red1(&sum_out[ix * k], l[k]);
        part = l[0];
    }
    // block-reduce k=0 bin (all edges hit index 0)
#pragma unroll
    for (int off = 16; off; off >>= 1)
        part += __shfl_down_sync(0xffffffffu, part, off);
    if ((tid & 31) == 0) sm[SM_RED + wq] = part;
    __syncthreads();
    if (tid == 0) {
        float a = 0.f;
#pragma unroll
        for (int i = 0; i < 8; i++) a += sm[SM_RED + i];
        red1(&sum_out[0], a);
    }
}

__global__ void k_scatter(const int* __restrict__ s_idx,
                          const int* __restrict__ o_idx) {
    int t = blockIdx.x * blockDim.x + threadIdx.x;
    if (t < NTt) {
        int s = s_idx[t], o = o_idx[t];
        g_perm_s[atomicAdd(&g_cur_s[s], 1)] = t;
        g_perm_o[atomicAdd(&g_cur_o[o], 1)] = t;
    }
}

// ------ layer-1 spmm, warp per o: weights loaded once, red into h[s] ------
__global__ void __launch_bounds__(256)
k_spmm1(const int* __restrict__ s_idx, const float* __restrict__ w1) {
    int w = (blockIdx.x * blockDim.x + threadIdx.x) >> 5;
    int lane = threadIdx.x & 31;
    if (w >= Nn) return;
    int o = w;
    int deg = g_deg_o[o];
    if (deg == 0) return;
    int beg = g_off_o[o];

    float wk[16];
#pragma unroll
    for (int k = 0; k < 16; k++) {
        int j = o * k;
        float c = g_colsum[j];                 // uniform across warp -> broadcast
        float inv = (c > 0.f) ? __frcp_rn(c) : 0.f;
        wk[k] = w1[(size_t)j * 32 + lane] * inv;
    }

    for (int p = beg; p < beg + deg; p++) {
        int t = g_perm_o[p];
        int s = s_idx[t];
        float lv = (lane < 16) ? g_lat1[(size_t)t * 16 + lane] : 0.f;
        float acc = 0.f;
#pragma unroll
        for (int k = 0; k < 16; k++)
            acc += __shfl_sync(0xffffffffu, lv, k) * wk[k];
        red1(&g_h[s * 32 + lane], acc);
    }
}

// ------------------------- h = relu(h + bias1) -----------------------------
__global__ void k_relu(const float* __restrict__ bias1) {
    int i = blockIdx.x * blockDim.x + threadIdx.x;
    if (i < Nn * Ee)
        g_h[i] = fmaxf(g_h[i] + bias1[i & 31], 0.f);
}

// ------------------------- layer-2 spmm into h2 (warp per s) --------------
__global__ void __launch_bounds__(256)
k_spmm2(const int* __restrict__ o_idx) {
    __shared__ __align__(16) float stage[8][16 * 32];
    int wid = threadIdx.x >> 5, lane = threadIdx.x & 31;
    int s = blockIdx.x * 8 + wid;
    if (s >= Nn) return;
    int deg = g_deg_s[s];
    if (deg == 0) return;
    int beg = g_off_s[s];
    float acc[16];
#pragma unroll
    for (int k = 0; k < 16; k++) acc[k] = 0.f;
    for (int p = beg; p < beg + deg; p++) {
        int t = g_perm_s[p];
        int o = o_idx[t];
        float hv = g_h[o * 32 + lane];
        float lv = (lane < 16) ? g_lat2[(size_t)t * 16 + lane] : 0.f;
#pragma unroll
        for (int k = 0; k < 16; k++)
            acc[k] += __shfl_sync(0xffffffffu, lv, k) * hv;
    }
    float* st = stage[wid];
#pragma unroll
    for (int k = 0; k < 16; k++) st[k * 32 + lane] = acc[k];
    __syncwarp();
#pragma unroll
    for (int it = 0; it < 4; it++) {
        int idx = it * 32 + lane;        // 0..127 over 16 rows x 8 float4
        int k = idx >> 3, q = idx & 7;
        float4 v = ((float4*)st)[idx];
        int j = s * k;
        red4(&((float4*)g_h2)[(size_t)j * 8 + q], v);
    }
}

// ------------------- einsum + bias2: out, 2 nodes / thread ----------------
__global__ void __launch_bounds__(256)
k_out(const float* __restrict__ w2, const float* __restrict__ bias2,
      float* __restrict__ out) {
    extern __shared__ __align__(16) float sw2[];   // 16*32*32 floats = 64 KB
    for (int i = threadIdx.x; i < 16 * 32 * 32; i += 256) sw2[i] = w2[i];
    __syncthreads();
    int n0 = blockIdx.x * 256 + threadIdx.x;       // 0..24999
    if (n0 >= Nn / 2) return;
    int n1 = n0 + Nn / 2;
    ULL accA[16], accB[16];
#pragma unroll
    for (int c2 = 0; c2 < 16; c2++) {
        accA[c2] = ((const ULL*)bias2)[c2];
        accB[c2] = accA[c2];
    }
#pragma unroll 1
    for (int r = 0; r < 16; r++) {
        int jA = r * Nn + n0;
        int jB = jA + Nn / 2;
        float ra = g_rowsum[jA], rb = g_rowsum[jB];
        float invA = (ra > 0.f) ? __frcp_rn(ra) : 0.f;
        float invB = (rb > 0.f) ? __frcp_rn(rb) : 0.f;
        const float4* hA = (const float4*)&g_h2[(size_t)jA * 32];
        const float4* hB = (const float4*)&g_h2[(size_t)jB * 32];
#pragma unroll
        for (int e4 = 0; e4 < 8; e4++) {
            float4 va = hA[e4];
            float4 vb = hB[e4];
            float xa[4] = { va.x * invA, va.y * invA, va.z * invA, va.w * invA };
            float xb[4] = { vb.x * invB, vb.y * invB, vb.z * invB, vb.w * invB };
#pragma unroll
            for (int u = 0; u < 4; u++) {
                int e = e4 * 4 + u;
                ULL sa = splat2(xa[u]);
                ULL sb = splat2(xb[u]);
                const float4* wr4 = (const float4*)&sw2[(r * 32 + e) * 32];
#pragma unroll
                for (int c4 = 0; c4 < 8; c4++) {
                    F4U w; w.f = wr4[c4];          // one LDS.128 feeds 4 ffma2
                    accA[2 * c4]     = ffma2(sa, w.u[0], accA[2 * c4]);
                    accA[2 * c4 + 1] = ffma2(sa, w.u[1], accA[2 * c4 + 1]);
                    accB[2 * c4]     = ffma2(sb, w.u[0], accB[2 * c4]);
                    accB[2 * c4 + 1] = ffma2(sb, w.u[1], accB[2 * c4 + 1]);
                }
            }
        }
    }
    ULL* opA = (ULL*)(out + (size_t)n0 * 32);
    ULL* opB = (ULL*)(out + (size_t)n1 * 32);
#pragma unroll
    for (int c2 = 0; c2 < 16; c2++) { opA[c2] = accA[c2]; opB[c2] = accB[c2]; }
}

// ------------------------- launch -----------------------------------------
extern "C" void kernel_launch(void* const* d_in, const int* in_sizes, int n_in,
                              void* d_out, int out_size) {
    const int*   s_idx = (const int*)d_in[0];
    const int*   o_idx = (const int*)d_in[1];
    const float* nhots = (const float*)d_in[2];
    const float* W1a   = (const float*)d_in[3];
    const float* b1a   = (const float*)d_in[4];
    const float* W1b   = (const float*)d_in[5];
    const float* b1b   = (const float*)d_in[6];
    const float* W2a   = (const float*)d_in[7];
    const float* b2a   = (const float*)d_in[8];
    const float* W2b   = (const float*)d_in[9];
    const float* b2b   = (const float*)d_in[10];
    const float* w1    = (const float*)d_in[11];
    const float* w2    = (const float*)d_in[12];
    const float* bias1 = (const float*)d_in[13];
    const float* bias2 = (const float*)d_in[14];
    float* out = (float*)d_out;

    static float* lat1p = nullptr;
    static float* lat2p = nullptr;
    static float* colp = nullptr;
    static float* rowp = nullptr;
    if (!lat1p) {
        cudaGetSymbolAddress((void**)&lat1p, g_lat1);
        cudaGetSymbolAddress((void**)&lat2p, g_lat2);
        cudaGetSymbolAddress((void**)&colp, g_colsum);
        cudaGetSymbolAddress((void**)&rowp, g_rowsum);
        cudaFuncSetAttribute(k_mlpg<1>, cudaFuncAttributeMaxDynamicSharedMemorySize,
                             SM_FLOATS * (int)sizeof(float));
        cudaFuncSetAttribute(k_mlpg<2>, cudaFuncAttributeMaxDynamicSharedMemorySize,
                             SM_FLOATS * (int)sizeof(float));
        cudaFuncSetAttribute(k_out, cudaFuncAttributeMaxDynamicSharedMemorySize,
                             16 * 32 * 32 * (int)sizeof(float));
    }

    int mlp_blocks = (NTt + 127) / 128;
    size_t mlp_smem = SM_FLOATS * sizeof(float);

    k_init<<<2048, 256>>>();                                   // 0
    k_deg<<<(NTt + 255) / 256, 256>>>(s_idx, o_idx);           // 1
    k_alloc<<<(Nn + 255) / 256, 256>>>();                      // 2
    k_mlpg<1><<<mlp_blocks, 256, mlp_smem>>>(o_idx, nhots,     // 3 <- ncu slot
                                             W1a, b1a, W1b, b1b, lat1p, colp);
    k_mlpg<2><<<mlp_blocks, 256, mlp_smem>>>(s_idx, nhots,     // 4
                                             W2a, b2a, W2b, b2b, lat2p, rowp);
    k_scatter<<<(NTt + 255) / 256, 256>>>(s_idx, o_idx);       // 5
    k_spmm1<<<(Nn * 32 + 255) / 256, 256>>>(s_idx, w1);        // 6
    k_relu<<<(Nn * Ee + 255) / 256, 256>>>(bias1);             // 7
    k_spmm2<<<(Nn + 7) / 8, 256>>>(o_idx);                     // 8
    k_out<<<(Nn / 2 + 255) / 256, 256, 16 * 32 * 32 * (int)sizeof(float)>>>(w2, bias2, out); // 9
}

// round 5
// speedup vs baseline: 1.3740x; 1.0527x over previous
#include <cuda_runtime.h>
#include <cstdint>

#define Nn  50000
#define NTt 300000
#define RPk 16
#define Ee  32
#define Cc  32

// ------------------------- device scratch (static, no allocs) -------------
__device__ float g_lat1[(size_t)NTt * RPk];        // 19.2 MB
__device__ float g_lat2[(size_t)NTt * RPk];        // 19.2 MB
__device__ float g_colsum[Nn * RPk];               // 3.2 MB
__device__ float g_rowsum[Nn * RPk];               // 3.2 MB
__device__ float g_h[Nn * Ee];                     // 6.4 MB
__device__ float g_h2[(size_t)RPk * Nn * Ee];      // 102.4 MB
__device__ int   g_deg_s[Nn];
__device__ int   g_deg_o[Nn];
__device__ int   g_off_s[Nn];
__device__ int   g_off_o[Nn];
__device__ int   g_cur_s[Nn];
__device__ int   g_cur_o[Nn];
__device__ int   g_perm_s[NTt];
__device__ int   g_perm_o[NTt];
__device__ int   g_counter[2];

// ------------------------- small helpers ----------------------------------
typedef unsigned long long ULL;
union F4U { float4 f; ULL u[2]; float s[4]; };

__device__ __forceinline__ ULL splat2(float v) {
    ULL r;
    asm("mov.b64 %0, {%1, %1};" : "=l"(r) : "f"(v));
    return r;
}
__device__ __forceinline__ ULL ffma2(ULL a, ULL b, ULL c) {
    ULL d;
    asm("fma.rn.f32x2 %0, %1, %2, %3;" : "=l"(d) : "l"(a), "l"(b), "l"(c));
    return d;
}
__device__ __forceinline__ void red4(float4* a, float4 v) {
    asm volatile("red.global.add.v4.f32 [%0], {%1, %2, %3, %4};"
                 :: "l"(a), "f"(v.x), "f"(v.y), "f"(v.z), "f"(v.w) : "memory");
}
__device__ __forceinline__ void red1(float* a, float v) {
    asm volatile("red.global.add.f32 [%0], %1;" :: "l"(a), "f"(v) : "memory");
}

// ------------------------- init: zero scratch -----------------------------
__global__ void k_init() {
    size_t i = (size_t)blockIdx.x * blockDim.x + threadIdx.x;
    size_t stride = (size_t)gridDim.x * blockDim.x;
    float4 z = make_float4(0.f, 0.f, 0.f, 0.f);
    for (size_t p = i; p < (size_t)RPk * Nn * Ee / 4; p += stride)
        ((float4*)g_h2)[p] = z;
    for (size_t p = i; p < (size_t)Nn * RPk / 4; p += stride) {
        ((float4*)g_colsum)[p] = z;
        ((float4*)g_rowsum)[p] = z;
    }
    for (size_t p = i; p < (size_t)Nn * Ee / 4; p += stride)
        ((float4*)g_h)[p] = z;
    for (size_t p = i; p < Nn / 4; p += stride) {
        ((int4*)g_deg_s)[p] = make_int4(0, 0, 0, 0);
        ((int4*)g_deg_o)[p] = make_int4(0, 0, 0, 0);
    }
    if (i == 0) { g_counter[0] = 0; g_counter[1] = 0; }
}

// ------------------------- degree count -----------------------------------
__global__ void k_deg(const int* __restrict__ s_idx, const int* __restrict__ o_idx) {
    int t = blockIdx.x * blockDim.x + threadIdx.x;
    if (t < NTt) {
        atomicAdd(&g_deg_s[s_idx[t]], 1);
        atomicAdd(&g_deg_o[o_idx[t]], 1);
    }
}

// ---------------- CSR range allocation (warp-aggregated, unordered) -------
__global__ void k_alloc() {
    int i = blockIdx.x * blockDim.x + threadIdx.x;
    int lane = threadIdx.x & 31;
    int ds = (i < Nn) ? g_deg_s[i] : 0;
    int dq = (i < Nn) ? g_deg_o[i] : 0;
    int ss = ds, so = dq;
#pragma unroll
    for (int off = 1; off < 32; off <<= 1) {
        int a = __shfl_up_sync(0xffffffffu, ss, off);
        int b = __shfl_up_sync(0xffffffffu, so, off);
        if (lane >= off) { ss += a; so += b; }
    }
    int bs = 0, bo = 0;
    if (lane == 31) {
        bs = atomicAdd(&g_counter[0], ss);
        bo = atomicAdd(&g_counter[1], so);
    }
    bs = __shfl_sync(0xffffffffu, bs, 31);
    bo = __shfl_sync(0xffffffffu, bo, 31);
    if (i < Nn) {
        int es = bs + ss - ds;
        int eo = bo + so - dq;
        g_off_s[i] = es; g_cur_s[i] = es;
        g_off_o[i] = eo; g_cur_o[i] = eo;
    }
}

// ------------- fused block-GEMM MLP + softmax + segment sum ---------------
// block = 128 edges, 256 threads. Weights via uniform LDG (L1-resident).
// smem (floats): X[128][65] @0 (reused as lat[128][17]); H[128][67] @8320; red @16896
#define SM_X   0
#define SM_H   8320
#define SM_RED 16896
#define SM_FLOATS 16904

__device__ __forceinline__ void softmax16(float* l) {
    float m = l[0];
#pragma unroll
    for (int k = 1; k < 16; k++) m = fmaxf(m, l[k]);
    float s = 0.f;
#pragma unroll
    for (int k = 0; k < 16; k++) { l[k] = __expf(l[k] - m); s += l[k]; }
    float inv = 1.f / s;
#pragma unroll
    for (int k = 0; k < 16; k++) l[k] *= inv;
}

template<int WHICH>
__global__ void __launch_bounds__(256)
k_mlpg(const int* __restrict__ nidx,          // o_idx (WHICH=1) / s_idx (WHICH=2)
       const float* __restrict__ nhots,
       const float* __restrict__ Wa, const float* __restrict__ ba,
       const float* __restrict__ Wb, const float* __restrict__ bb,
       float* __restrict__ lat_out, float* __restrict__ sum_out) {
    extern __shared__ __align__(16) float sm[];
    int tid = threadIdx.x;
    int e_base = blockIdx.x * 128;

    // ---- stage X [128 edges][64] into sm+SM_X, row pad 65 ----
#pragma unroll
    for (int j = 0; j < 8; j++) {
        int idx4 = tid + 256 * j;            // 0..2047 float4 slots
        int e = idx4 >> 4, kq = idx4 & 15;
        float4 v = make_float4(0.f, 0.f, 0.f, 0.f);
        if (e_base + e < NTt)
            v = __ldg((const float4*)(nhots + (size_t)(e_base + e) * 64) + kq);
        float* dst = sm + SM_X + e * 65 + kq * 4;
        dst[0] = v.x; dst[1] = v.y; dst[2] = v.z; dst[3] = v.w;
    }
    __syncthreads();

    int lane = tid & 31, wq = tid >> 5;

    // ---- phase 1: H[128][64] = relu(X @ Wa + ba); thread: 4 edges x 8 hid --
    {
        int h0 = wq * 8;
        ULL acc[4][4];
        ULL b0 = __ldg((const ULL*)(ba + h0));
        ULL b1 = __ldg((const ULL*)(ba + h0 + 2));
        ULL b2 = __ldg((const ULL*)(ba + h0 + 4));
        ULL b3 = __ldg((const ULL*)(ba + h0 + 6));
#pragma unroll
        for (int i = 0; i < 4; i++) {
            acc[i][0] = b0; acc[i][1] = b1; acc[i][2] = b2; acc[i][3] = b3;
        }
#pragma unroll 2
        for (int k = 0; k < 64; k++) {
            float x0 = sm[SM_X + lane * 65 + k];
            float x1 = sm[SM_X + (lane + 32) * 65 + k];
            float x2 = sm[SM_X + (lane + 64) * 65 + k];
            float x3 = sm[SM_X + (lane + 96) * 65 + k];
            F4U wA; wA.f = __ldg((const float4*)(Wa + k * 64 + h0));
            F4U wB; wB.f = __ldg((const float4*)(Wa + k * 64 + h0 + 4));
            ULL s0 = splat2(x0), s1 = splat2(x1), s2 = splat2(x2), s3 = splat2(x3);
            acc[0][0] = ffma2(s0, wA.u[0], acc[0][0]);
            acc[0][1] = ffma2(s0, wA.u[1], acc[0][1]);
            acc[0][2] = ffma2(s0, wB.u[0], acc[0][2]);
            acc[0][3] = ffma2(s0, wB.u[1], acc[0][3]);
            acc[1][0] = ffma2(s1, wA.u[0], acc[1][0]);
            acc[1][1] = ffma2(s1, wA.u[1], acc[1][1]);
            acc[1][2] = ffma2(s1, wB.u[0], acc[1][2]);
            acc[1][3] = ffma2(s1, wB.u[1], acc[1][3]);
            acc[2][0] = ffma2(s2, wA.u[0], acc[2][0]);
            acc[2][1] = ffma2(s2, wA.u[1], acc[2][1]);
            acc[2][2] = ffma2(s2, wB.u[0], acc[2][2]);
            acc[2][3] = ffma2(s2, wB.u[1], acc[2][3]);
            acc[3][0] = ffma2(s3, wA.u[0], acc[3][0]);
            acc[3][1] = ffma2(s3, wA.u[1], acc[3][1]);
            acc[3][2] = ffma2(s3, wB.u[0], acc[3][2]);
            acc[3][3] = ffma2(s3, wB.u[1], acc[3][3]);
        }
        // relu + store H (pad 67)
#pragma unroll
        for (int i = 0; i < 4; i++) {
            float* hr = sm + SM_H + (lane + 32 * i) * 67 + h0;
#pragma unroll
            for (int q = 0; q < 4; q++) {
                float2 v = *(float2*)&acc[i][q];
                hr[2 * q]     = fmaxf(v.x, 0.f);
                hr[2 * q + 1] = fmaxf(v.y, 0.f);
            }
        }
    }
    __syncthreads();

    // ---- phase 2: lat[128][16] = H @ Wb + bb; thread: 4 edges x 2 classes --
    {
        int c0 = wq * 2;
        ULL a2[4];
        ULL binit = __ldg((const ULL*)(bb + c0));
#pragma unroll
        for (int i = 0; i < 4; i++) a2[i] = binit;
#pragma unroll 2
        for (int j = 0; j < 64; j++) {
            float h0v = sm[SM_H + lane * 67 + j];
            float h1v = sm[SM_H + (lane + 32) * 67 + j];
            float h2v = sm[SM_H + (lane + 64) * 67 + j];
            float h3v = sm[SM_H + (lane + 96) * 67 + j];
            ULL wb = __ldg((const ULL*)(Wb + j * 16 + c0));
            a2[0] = ffma2(splat2(h0v), wb, a2[0]);
            a2[1] = ffma2(splat2(h1v), wb, a2[1]);
            a2[2] = ffma2(splat2(h2v), wb, a2[2]);
            a2[3] = ffma2(splat2(h3v), wb, a2[3]);
        }
        __syncthreads();   // everyone done reading H/X before lat overlays X
        // store lat into X region, row pad 17
#pragma unroll
        for (int i = 0; i < 4; i++) {
            float2 v = *(float2*)&a2[i];
            float* lr = sm + SM_X + (lane + 32 * i) * 17 + c0;
            lr[0] = v.x; lr[1] = v.y;
        }
    }
    __syncthreads();

    // ---- epilogue: softmax, emit latents, segment-sum atomics ----
    float part = 0.f;
    if (tid < 128 && e_base + tid < NTt) {
        int e = e_base + tid;
        float l[16];
        const float* lr = sm + SM_X + tid * 17;
#pragma unroll
        for (int c = 0; c < 16; c++) l[c] = lr[c];
        softmax16(l);
        float4* po = (float4*)(lat_out + (size_t)e * 16);
#pragma unroll
        for (int q = 0; q < 4; q++)
            po[q] = make_float4(l[4 * q], l[4 * q + 1], l[4 * q + 2], l[4 * q + 3]);
        int ix = nidx[e];
#pragma unroll
        for (int k = 1; k < 16; k++)
            red1(&sum_out[ix * k], l[k]);
        part = l[0];
    }
    // block-reduce k=0 bin (all edges hit index 0)
#pragma unroll
    for (int off = 16; off; off >>= 1)
        part += __shfl_down_sync(0xffffffffu, part, off);
    if ((tid & 31) == 0) sm[SM_RED + wq] = part;
    __syncthreads();
    if (tid == 0) {
        float a = 0.f;
#pragma unroll
        for (int i = 0; i < 8; i++) a += sm[SM_RED + i];
        red1(&sum_out[0], a);
    }
}

__global__ void k_scatter(const int* __restrict__ s_idx,
                          const int* __restrict__ o_idx) {
    int t = blockIdx.x * blockDim.x + threadIdx.x;
    if (t < NTt) {
        int s = s_idx[t], o = o_idx[t];
        g_perm_s[atomicAdd(&g_cur_s[s], 1)] = t;
        g_perm_o[atomicAdd(&g_cur_o[o], 1)] = t;
    }
}

// ------ layer-1 spmm, warp per o: weights loaded once, red into h[s] ------
__global__ void __launch_bounds__(256)
k_spmm1(const int* __restrict__ s_idx, const float* __restrict__ w1) {
    int w = (blockIdx.x * blockDim.x + threadIdx.x) >> 5;
    int lane = threadIdx.x & 31;
    if (w >= Nn) return;
    int o = w;
    int deg = g_deg_o[o];
    if (deg == 0) return;
    int beg = g_off_o[o];

    float wk[16];
#pragma unroll
    for (int k = 0; k < 16; k++) {
        int j = o * k;
        float c = g_colsum[j];                 // uniform across warp -> broadcast
        float inv = (c > 0.f) ? __frcp_rn(c) : 0.f;
        wk[k] = w1[(size_t)j * 32 + lane] * inv;
    }

    for (int p = beg; p < beg + deg; p++) {
        int t = g_perm_o[p];
        int s = s_idx[t];
        float lv = (lane < 16) ? g_lat1[(size_t)t * 16 + lane] : 0.f;
        float acc = 0.f;
#pragma unroll
        for (int k = 0; k < 16; k++)
            acc += __shfl_sync(0xffffffffu, lv, k) * wk[k];
        red1(&g_h[s * 32 + lane], acc);
    }
}

// ------------------------- h = relu(h + bias1) -----------------------------
__global__ void k_relu(const float* __restrict__ bias1) {
    int i = blockIdx.x * blockDim.x + threadIdx.x;
    if (i < Nn * Ee)
        g_h[i] = fmaxf(g_h[i] + bias1[i & 31], 0.f);
}

// -------- h2 row j=0 (k=0 bin): block-aggregated global reduction ---------
__global__ void __launch_bounds__(256)
k_h2k0(const int* __restrict__ o_idx) {
    __shared__ float sacc[8][32];
    int lane = threadIdx.x & 31, wid = threadIdx.x >> 5;
    int gw = blockIdx.x * 8 + wid;
    int nw = gridDim.x * 8;
    float acc = 0.f;
    for (int t = gw; t < NTt; t += nw) {
        float l0 = __ldg(&g_lat2[(size_t)t * 16]);
        int o = __ldg(&o_idx[t]);
        acc += l0 * g_h[o * 32 + lane];
    }
    sacc[wid][lane] = acc;
    __syncthreads();
    if (wid == 0) {
        float tot = 0.f;
#pragma unroll
        for (int i = 0; i < 8; i++) tot += sacc[i][lane];
        red1(&g_h2[lane], tot);
    }
}

// --------------- layer-2 spmm into h2 (warp per s, k>=1 only) -------------
__global__ void __launch_bounds__(256)
k_spmm2(const int* __restrict__ o_idx) {
    __shared__ __align__(16) float stage[8][16 * 32];
    int wid = threadIdx.x >> 5, lane = threadIdx.x & 31;
    int s = blockIdx.x * 8 + wid;
    if (s >= Nn) return;
    int deg = g_deg_s[s];
    if (deg == 0) return;
    int beg = g_off_s[s];
    float acc[16];
#pragma unroll
    for (int k = 0; k < 16; k++) acc[k] = 0.f;
    for (int p = beg; p < beg + deg; p++) {
        int t = g_perm_s[p];
        int o = o_idx[t];
        float hv = g_h[o * 32 + lane];
        float lv = (lane < 16) ? g_lat2[(size_t)t * 16 + lane] : 0.f;
#pragma unroll
        for (int k = 1; k < 16; k++)
            acc[k] += __shfl_sync(0xffffffffu, lv, k) * hv;
    }
    float* st = stage[wid];
#pragma unroll
    for (int k = 1; k < 16; k++) st[k * 32 + lane] = acc[k];
    __syncwarp();
#pragma unroll
    for (int it = 0; it < 4; it++) {
        int idx = it * 32 + lane;        // 0..127 over 16 rows x 8 float4
        if (idx >= 8) {                  // skip k=0 (handled by k_h2k0)
            int k = idx >> 3, q = idx & 7;
            float4 v = ((float4*)st)[idx];
            int j = s * k;
            red4(&((float4*)g_h2)[(size_t)j * 8 + q], v);
        }
    }
}

// ------------------- einsum + bias2: out, 2 nodes / thread ----------------
__global__ void __launch_bounds__(256)
k_out(const float* __restrict__ w2, const float* __restrict__ bias2,
      float* __restrict__ out) {
    extern __shared__ __align__(16) float sw2[];   // 16*32*32 floats = 64 KB
    for (int i = threadIdx.x; i < 16 * 32 * 32; i += 256) sw2[i] = w2[i];
    __syncthreads();
    int n0 = blockIdx.x * 256 + threadIdx.x;       // 0..24999
    if (n0 >= Nn / 2) return;
    int n1 = n0 + Nn / 2;
    ULL accA[16], accB[16];
#pragma unroll
    for (int c2 = 0; c2 < 16; c2++) {
        accA[c2] = ((const ULL*)bias2)[c2];
        accB[c2] = accA[c2];
    }
#pragma unroll 1
    for (int r = 0; r < 16; r++) {
        int jA = r * Nn + n0;
        int jB = jA + Nn / 2;
        float ra = g_rowsum[jA], rb = g_rowsum[jB];
        float invA = (ra > 0.f) ? __frcp_rn(ra) : 0.f;
        float invB = (rb > 0.f) ? __frcp_rn(rb) : 0.f;
        const float4* hA = (const float4*)&g_h2[(size_t)jA * 32];
        const float4* hB = (const float4*)&g_h2[(size_t)jB * 32];
#pragma unroll
        for (int e4 = 0; e4 < 8; e4++) {
            float4 va = hA[e4];
            float4 vb = hB[e4];
            float xa[4] = { va.x * invA, va.y * invA, va.z * invA, va.w * invA };
            float xb[4] = { vb.x * invB, vb.y * invB, vb.z * invB, vb.w * invB };
#pragma unroll
            for (int u = 0; u < 4; u++) {
                int e = e4 * 4 + u;
                ULL sa = splat2(xa[u]);
                ULL sb = splat2(xb[u]);
                const float4* wr4 = (const float4*)&sw2[(r * 32 + e) * 32];
#pragma unroll
                for (int c4 = 0; c4 < 8; c4++) {
                    F4U w; w.f = wr4[c4];          // one LDS.128 feeds 4 ffma2
                    accA[2 * c4]     = ffma2(sa, w.u[0], accA[2 * c4]);
                    accA[2 * c4 + 1] = ffma2(sa, w.u[1], accA[2 * c4 + 1]);
                    accB[2 * c4]     = ffma2(sb, w.u[0], accB[2 * c4]);
                    accB[2 * c4 + 1] = ffma2(sb, w.u[1], accB[2 * c4 + 1]);
                }
            }
        }
    }
    ULL* opA = (ULL*)(out + (size_t)n0 * 32);
    ULL* opB = (ULL*)(out + (size_t)n1 * 32);
#pragma unroll
    for (int c2 = 0; c2 < 16; c2++) { opA[c2] = accA[c2]; opB[c2] = accB[c2]; }
}

// ------------------------- launch -----------------------------------------
extern "C" void kernel_launch(void* const* d_in, const int* in_sizes, int n_in,
                              void* d_out, int out_size) {
    const int*   s_idx = (const int*)d_in[0];
    const int*   o_idx = (const int*)d_in[1];
    const float* nhots = (const float*)d_in[2];
    const float* W1a   = (const float*)d_in[3];
    const float* b1a   = (const float*)d_in[4];
    const float* W1b   = (const float*)d_in[5];
    const float* b1b   = (const float*)d_in[6];
    const float* W2a   = (const float*)d_in[7];
    const float* b2a   = (const float*)d_in[8];
    const float* W2b   = (const float*)d_in[9];
    const float* b2b   = (const float*)d_in[10];
    const float* w1    = (const float*)d_in[11];
    const float* w2    = (const float*)d_in[12];
    const float* bias1 = (const float*)d_in[13];
    const float* bias2 = (const float*)d_in[14];
    float* out = (float*)d_out;

    static float* lat1p = nullptr;
    static float* lat2p = nullptr;
    static float* colp = nullptr;
    static float* rowp = nullptr;
    if (!lat1p) {
        cudaGetSymbolAddress((void**)&lat1p, g_lat1);
        cudaGetSymbolAddress((void**)&lat2p, g_lat2);
        cudaGetSymbolAddress((void**)&colp, g_colsum);
        cudaGetSymbolAddress((void**)&rowp, g_rowsum);
        cudaFuncSetAttribute(k_mlpg<1>, cudaFuncAttributeMaxDynamicSharedMemorySize,
                             SM_FLOATS * (int)sizeof(float));
        cudaFuncSetAttribute(k_mlpg<2>, cudaFuncAttributeMaxDynamicSharedMemorySize,
                             SM_FLOATS * (int)sizeof(float));
        cudaFuncSetAttribute(k_out, cudaFuncAttributeMaxDynamicSharedMemorySize,
                             16 * 32 * 32 * (int)sizeof(float));
    }

    int mlp_blocks = (NTt + 127) / 128;
    size_t mlp_smem = SM_FLOATS * sizeof(float);

    k_init<<<2048, 256>>>();                                   // 0
    k_deg<<<(NTt + 255) / 256, 256>>>(s_idx, o_idx);           // 1
    k_alloc<<<(Nn + 255) / 256, 256>>>();                      // 2
    k_mlpg<1><<<mlp_blocks, 256, mlp_smem>>>(o_idx, nhots,     // 3 <- ncu slot
                                             W1a, b1a, W1b, b1b, lat1p, colp);
    k_mlpg<2><<<mlp_blocks, 256, mlp_smem>>>(s_idx, nhots,     // 4
                                             W2a, b2a, W2b, b2b, lat2p, rowp);
    k_scatter<<<(NTt + 255) / 256, 256>>>(s_idx, o_idx);       // 5
    k_spmm1<<<(Nn * 32 + 255) / 256, 256>>>(s_idx, w1);        // 6
    k_relu<<<(Nn * Ee + 255) / 256, 256>>>(bias1);             // 7
    k_h2k0<<<512, 256>>>(o_idx);                               // 8
    k_spmm2<<<(Nn + 7) / 8, 256>>>(o_idx);                     // 9
    k_out<<<(Nn / 2 + 255) / 256, 256, 16 * 32 * 32 * (int)sizeof(float)>>>(w2, bias2, out); // 10
}

// round 6
// speedup vs baseline: 1.6147x; 1.1752x over previous
#include <cuda_runtime.h>
#include <cstdint>

#define Nn  50000
#define NTt 300000
#define RPk 16
#define Ee  32
#define Cc  32

// ------------------------- device scratch (static, no allocs) -------------
__device__ float g_lat1[(size_t)NTt * RPk];        // 19.2 MB
__device__ float g_lat2[(size_t)NTt * RPk];        // 19.2 MB
__device__ float g_colsum[Nn * RPk];               // 3.2 MB
__device__ float g_rowsum[Nn * RPk];               // 3.2 MB
__device__ float g_h[Nn * Ee];                     // 6.4 MB
__device__ float g_h2[(size_t)RPk * Nn * Ee];      // 102.4 MB
__device__ int   g_deg_s[Nn];
__device__ int   g_deg_o[Nn];
__device__ int   g_off_s[Nn];
__device__ int   g_off_o[Nn];
__device__ int   g_cur_s[Nn];
__device__ int   g_cur_o[Nn];
__device__ int   g_perm_s[NTt];
__device__ int   g_perm_o[NTt];
__device__ int   g_counter[2];

// ------------------------- small helpers ----------------------------------
typedef unsigned long long ULL;
union F4U { float4 f; ULL u[2]; float s[4]; };

__device__ __forceinline__ ULL splat2(float v) {
    ULL r;
    asm("mov.b64 %0, {%1, %1};" : "=l"(r) : "f"(v));
    return r;
}
__device__ __forceinline__ ULL ffma2(ULL a, ULL b, ULL c) {
    ULL d;
    asm("fma.rn.f32x2 %0, %1, %2, %3;" : "=l"(d) : "l"(a), "l"(b), "l"(c));
    return d;
}
__device__ __forceinline__ void red4(float4* a, float4 v) {
    asm volatile("red.global.add.v4.f32 [%0], {%1, %2, %3, %4};"
                 :: "l"(a), "f"(v.x), "f"(v.y), "f"(v.z), "f"(v.w) : "memory");
}
__device__ __forceinline__ void red1(float* a, float v) {
    asm volatile("red.global.add.f32 [%0], %1;" :: "l"(a), "f"(v) : "memory");
}

// ------------------------- init: zero scratch -----------------------------
__global__ void k_init() {
    size_t i = (size_t)blockIdx.x * blockDim.x + threadIdx.x;
    size_t stride = (size_t)gridDim.x * blockDim.x;
    float4 z = make_float4(0.f, 0.f, 0.f, 0.f);
    for (size_t p = i; p < (size_t)RPk * Nn * Ee / 4; p += stride)
        ((float4*)g_h2)[p] = z;
    for (size_t p = i; p < (size_t)Nn * RPk / 4; p += stride) {
        ((float4*)g_colsum)[p] = z;
        ((float4*)g_rowsum)[p] = z;
    }
    for (size_t p = i; p < (size_t)Nn * Ee / 4; p += stride)
        ((float4*)g_h)[p] = z;
    for (size_t p = i; p < Nn / 4; p += stride) {
        ((int4*)g_deg_s)[p] = make_int4(0, 0, 0, 0);
        ((int4*)g_deg_o)[p] = make_int4(0, 0, 0, 0);
    }
    if (i == 0) { g_counter[0] = 0; g_counter[1] = 0; }
}

// ------------------------- degree count -----------------------------------
__global__ void k_deg(const int* __restrict__ s_idx, const int* __restrict__ o_idx) {
    int t = blockIdx.x * blockDim.x + threadIdx.x;
    if (t < NTt) {
        atomicAdd(&g_deg_s[s_idx[t]], 1);
        atomicAdd(&g_deg_o[o_idx[t]], 1);
    }
}

// ---------------- CSR range allocation (warp-aggregated, unordered) -------
__global__ void k_alloc() {
    int i = blockIdx.x * blockDim.x + threadIdx.x;
    int lane = threadIdx.x & 31;
    int ds = (i < Nn) ? g_deg_s[i] : 0;
    int dq = (i < Nn) ? g_deg_o[i] : 0;
    int ss = ds, so = dq;
#pragma unroll
    for (int off = 1; off < 32; off <<= 1) {
        int a = __shfl_up_sync(0xffffffffu, ss, off);
        int b = __shfl_up_sync(0xffffffffu, so, off);
        if (lane >= off) { ss += a; so += b; }
    }
    int bs = 0, bo = 0;
    if (lane == 31) {
        bs = atomicAdd(&g_counter[0], ss);
        bo = atomicAdd(&g_counter[1], so);
    }
    bs = __shfl_sync(0xffffffffu, bs, 31);
    bo = __shfl_sync(0xffffffffu, bo, 31);
    if (i < Nn) {
        int es = bs + ss - ds;
        int eo = bo + so - dq;
        g_off_s[i] = es; g_cur_s[i] = es;
        g_off_o[i] = eo; g_cur_o[i] = eo;
    }
}

// --------- fused double-MLP + softmax + segment sums (one kernel) ---------
// block = 128 edges, 256 threads. smem layout (floats):
//   X    [128][65] @ 0      (8320)
//   H    [128][67] @ 8320   (8576)  -- reused for lat[128][17] per layer
//   W1   [64][64]  @ 16896  (4096)
//   W1b  [64][16]  @ 20992  (1024)
//   W2   [64][64]  @ 22016  (4096)
//   W2b  [64][16]  @ 26112  (1024)
//   B    ba1/bb1/ba2/bb2 @ 27136 (160)
//   red  @ 27296 (8)
#define SM_X    0
#define SM_H    8320
#define SM_W1   16896
#define SM_W1b  20992
#define SM_W2   22016
#define SM_W2b  26112
#define SM_BA1  27136
#define SM_BB1  27200
#define SM_BA2  27216
#define SM_BB2  27280
#define SM_RED  27296
#define SM_FLOATS 27304

__device__ __forceinline__ void softmax16(float* l) {
    float m = l[0];
#pragma unroll
    for (int k = 1; k < 16; k++) m = fmaxf(m, l[k]);
    float s = 0.f;
#pragma unroll
    for (int k = 0; k < 16; k++) { l[k] = __expf(l[k] - m); s += l[k]; }
    float inv = 1.f / s;
#pragma unroll
    for (int k = 0; k < 16; k++) l[k] *= inv;
}

__device__ __forceinline__ void mlp_layer(float* sm, int tid, int e_base,
                                          const float* sW, const float* sWb,
                                          const float* sba, const float* sbb,
                                          const int* __restrict__ nidx,
                                          float* __restrict__ lat_out,
                                          float* __restrict__ sum_out) {
    int lane = tid & 31, wq = tid >> 5;

    // ---- phase 1: H[128][64] = relu(X @ Wa + ba); thread: 4 edges x 8 hid --
    {
        int h0 = wq * 8;
        ULL acc[4][4];
        ULL b0 = *(ULL*)&sba[h0];
        ULL b1 = *(ULL*)&sba[h0 + 2];
        ULL b2 = *(ULL*)&sba[h0 + 4];
        ULL b3 = *(ULL*)&sba[h0 + 6];
#pragma unroll
        for (int i = 0; i < 4; i++) {
            acc[i][0] = b0; acc[i][1] = b1; acc[i][2] = b2; acc[i][3] = b3;
        }
#pragma unroll 2
        for (int k = 0; k < 64; k++) {
            float x0 = sm[SM_X + lane * 65 + k];
            float x1 = sm[SM_X + (lane + 32) * 65 + k];
            float x2 = sm[SM_X + (lane + 64) * 65 + k];
            float x3 = sm[SM_X + (lane + 96) * 65 + k];
            F4U wA; wA.f = *(const float4*)&sW[k * 64 + h0];
            F4U wB; wB.f = *(const float4*)&sW[k * 64 + h0 + 4];
            ULL s0 = splat2(x0), s1 = splat2(x1), s2 = splat2(x2), s3 = splat2(x3);
            acc[0][0] = ffma2(s0, wA.u[0], acc[0][0]);
            acc[0][1] = ffma2(s0, wA.u[1], acc[0][1]);
            acc[0][2] = ffma2(s0, wB.u[0], acc[0][2]);
            acc[0][3] = ffma2(s0, wB.u[1], acc[0][3]);
            acc[1][0] = ffma2(s1, wA.u[0], acc[1][0]);
            acc[1][1] = ffma2(s1, wA.u[1], acc[1][1]);
            acc[1][2] = ffma2(s1, wB.u[0], acc[1][2]);
            acc[1][3] = ffma2(s1, wB.u[1], acc[1][3]);
            acc[2][0] = ffma2(s2, wA.u[0], acc[2][0]);
            acc[2][1] = ffma2(s2, wA.u[1], acc[2][1]);
            acc[2][2] = ffma2(s2, wB.u[0], acc[2][2]);
            acc[2][3] = ffma2(s2, wB.u[1], acc[2][3]);
            acc[3][0] = ffma2(s3, wA.u[0], acc[3][0]);
            acc[3][1] = ffma2(s3, wA.u[1], acc[3][1]);
            acc[3][2] = ffma2(s3, wB.u[0], acc[3][2]);
            acc[3][3] = ffma2(s3, wB.u[1], acc[3][3]);
        }
        // relu + store H (pad 67)
#pragma unroll
        for (int i = 0; i < 4; i++) {
            float* hr = sm + SM_H + (lane + 32 * i) * 67 + h0;
#pragma unroll
            for (int q = 0; q < 4; q++) {
                float2 v = *(float2*)&acc[i][q];
                hr[2 * q]     = fmaxf(v.x, 0.f);
                hr[2 * q + 1] = fmaxf(v.y, 0.f);
            }
        }
    }
    __syncthreads();

    // ---- phase 2: lat[128][16] = H @ Wb + bb; thread: 4 edges x 2 classes --
    {
        int c0 = wq * 2;
        ULL a2[4];
        ULL binit = *(ULL*)&sbb[c0];
#pragma unroll
        for (int i = 0; i < 4; i++) a2[i] = binit;
#pragma unroll 2
        for (int j = 0; j < 64; j++) {
            float h0v = sm[SM_H + lane * 67 + j];
            float h1v = sm[SM_H + (lane + 32) * 67 + j];
            float h2v = sm[SM_H + (lane + 64) * 67 + j];
            float h3v = sm[SM_H + (lane + 96) * 67 + j];
            ULL wb = *(const ULL*)&sWb[j * 16 + c0];
            a2[0] = ffma2(splat2(h0v), wb, a2[0]);
            a2[1] = ffma2(splat2(h1v), wb, a2[1]);
            a2[2] = ffma2(splat2(h2v), wb, a2[2]);
            a2[3] = ffma2(splat2(h3v), wb, a2[3]);
        }
        __syncthreads();   // all H reads done before lat overlays H region
#pragma unroll
        for (int i = 0; i < 4; i++) {
            float2 v = *(float2*)&a2[i];
            float* lr = sm + SM_H + (lane + 32 * i) * 17 + c0;
            lr[0] = v.x; lr[1] = v.y;
        }
    }
    __syncthreads();

    // ---- epilogue: softmax, emit latents, segment-sum atomics ----
    float part = 0.f;
    if (tid < 128 && e_base + tid < NTt) {
        int e = e_base + tid;
        float l[16];
        const float* lr = sm + SM_H + tid * 17;
#pragma unroll
        for (int c = 0; c < 16; c++) l[c] = lr[c];
        softmax16(l);
        float4* po = (float4*)(lat_out + (size_t)e * 16);
#pragma unroll
        for (int q = 0; q < 4; q++)
            po[q] = make_float4(l[4 * q], l[4 * q + 1], l[4 * q + 2], l[4 * q + 3]);
        int ix = nidx[e];
#pragma unroll
        for (int k = 1; k < 16; k++)
            red1(&sum_out[ix * k], l[k]);
        part = l[0];
    }
#pragma unroll
    for (int off = 16; off; off >>= 1)
        part += __shfl_down_sync(0xffffffffu, part, off);
    if ((tid & 31) == 0) sm[SM_RED + (tid >> 5)] = part;
    __syncthreads();
    if (tid == 0) {
        float a = 0.f;
#pragma unroll
        for (int i = 0; i < 8; i++) a += sm[SM_RED + i];
        red1(&sum_out[0], a);
    }
    __syncthreads();   // lat region (H) free before next layer writes H
}

__global__ void __launch_bounds__(256)
k_mlp(const int* __restrict__ s_idx, const int* __restrict__ o_idx,
      const float* __restrict__ nhots,
      const float* __restrict__ W1a, const float* __restrict__ b1a,
      const float* __restrict__ W1b, const float* __restrict__ b1b,
      const float* __restrict__ W2a, const float* __restrict__ b2a,
      const float* __restrict__ W2b, const float* __restrict__ b2b,
      float* __restrict__ lat1, float* __restrict__ lat2,
      float* __restrict__ colsum, float* __restrict__ rowsum) {
    extern __shared__ __align__(16) float sm[];
    int tid = threadIdx.x;
    int e_base = blockIdx.x * 128;

    // ---- stage X [128 edges][64], row pad 65 ----
#pragma unroll
    for (int j = 0; j < 8; j++) {
        int idx4 = tid + 256 * j;            // 0..2047 float4 slots
        int e = idx4 >> 4, kq = idx4 & 15;
        float4 v = make_float4(0.f, 0.f, 0.f, 0.f);
        if (e_base + e < NTt)
            v = __ldg((const float4*)(nhots + (size_t)(e_base + e) * 64) + kq);
        float* dst = sm + SM_X + e * 65 + kq * 4;
        dst[0] = v.x; dst[1] = v.y; dst[2] = v.z; dst[3] = v.w;
    }
    // ---- stage both weight sets ----
    for (int i = tid; i < 4096; i += 256) { sm[SM_W1 + i] = W1a[i]; sm[SM_W2 + i] = W2a[i]; }
    for (int i = tid; i < 1024; i += 256) { sm[SM_W1b + i] = W1b[i]; sm[SM_W2b + i] = W2b[i]; }
    if (tid < 64) { sm[SM_BA1 + tid] = b1a[tid]; sm[SM_BA2 + tid] = b2a[tid]; }
    if (tid < 16) { sm[SM_BB1 + tid] = b1b[tid]; sm[SM_BB2 + tid] = b2b[tid]; }
    __syncthreads();

    mlp_layer(sm, tid, e_base, sm + SM_W1, sm + SM_W1b, sm + SM_BA1, sm + SM_BB1,
              o_idx, lat1, colsum);
    mlp_layer(sm, tid, e_base, sm + SM_W2, sm + SM_W2b, sm + SM_BA2, sm + SM_BB2,
              s_idx, lat2, rowsum);
}

__global__ void k_scatter(const int* __restrict__ s_idx,
                          const int* __restrict__ o_idx) {
    int t = blockIdx.x * blockDim.x + threadIdx.x;
    if (t < NTt) {
        int s = s_idx[t], o = o_idx[t];
        g_perm_s[atomicAdd(&g_cur_s[s], 1)] = t;
        g_perm_o[atomicAdd(&g_cur_o[o], 1)] = t;
    }
}

// ------ layer-1 spmm, warp per o: weights loaded once, red into h[s] ------
__global__ void __launch_bounds__(256)
k_spmm1(const int* __restrict__ s_idx, const float* __restrict__ w1) {
    int w = (blockIdx.x * blockDim.x + threadIdx.x) >> 5;
    int lane = threadIdx.x & 31;
    if (w >= Nn) return;
    int o = w;
    int deg = g_deg_o[o];
    if (deg == 0) return;
    int beg = g_off_o[o], end = beg + deg;

    float wk[16];
#pragma unroll
    for (int k = 0; k < 16; k++) {
        int j = o * k;
        float c = g_colsum[j];                 // uniform across warp -> broadcast
        float inv = (c > 0.f) ? __frcp_rn(c) : 0.f;
        wk[k] = w1[(size_t)j * 32 + lane] * inv;
    }

    int t = __ldg(&g_perm_o[beg]);
    for (int p = beg; p < end; p++) {
        int tn = (p + 1 < end) ? __ldg(&g_perm_o[p + 1]) : t;  // prefetch next idx
        int s = __ldg(&s_idx[t]);
        float lv = (lane < 16) ? __ldg(&g_lat1[(size_t)t * 16 + lane]) : 0.f;
        float acc = 0.f;
#pragma unroll
        for (int k = 0; k < 16; k++)
            acc += __shfl_sync(0xffffffffu, lv, k) * wk[k];
        red1(&g_h[s * 32 + lane], acc);
        t = tn;
    }
}

// ------------------------- h = relu(h + bias1) -----------------------------
__global__ void k_relu(const float* __restrict__ bias1) {
    int i = blockIdx.x * blockDim.x + threadIdx.x;
    if (i < Nn * Ee)
        g_h[i] = fmaxf(g_h[i] + bias1[i & 31], 0.f);
}

// -------- h2 row j=0 (k=0 bin): block-aggregated global reduction ---------
__global__ void __launch_bounds__(256)
k_h2k0(const int* __restrict__ o_idx) {
    __shared__ float sacc[8][32];
    int lane = threadIdx.x & 31, wid = threadIdx.x >> 5;
    int gw = blockIdx.x * 8 + wid;
    int nw = gridDim.x * 8;
    float acc = 0.f;
    for (int t = gw; t < NTt; t += nw) {
        float l0 = __ldg(&g_lat2[(size_t)t * 16]);
        int o = __ldg(&o_idx[t]);
        acc += l0 * g_h[o * 32 + lane];
    }
    sacc[wid][lane] = acc;
    __syncthreads();
    if (wid == 0) {
        float tot = 0.f;
#pragma unroll
        for (int i = 0; i < 8; i++) tot += sacc[i][lane];
        red1(&g_h2[lane], tot);
    }
}

// --------------- layer-2 spmm into h2 (warp per s, k>=1 only) -------------
__global__ void __launch_bounds__(256)
k_spmm2(const int* __restrict__ o_idx) {
    __shared__ __align__(16) float stage[8][16 * 32];
    int wid = threadIdx.x >> 5, lane = threadIdx.x & 31;
    int s = blockIdx.x * 8 + wid;
    if (s >= Nn) return;
    int deg = g_deg_s[s];
    if (deg == 0) return;
    int beg = g_off_s[s], end = beg + deg;
    float acc[16];
#pragma unroll
    for (int k = 0; k < 16; k++) acc[k] = 0.f;
    int t = __ldg(&g_perm_s[beg]);
    for (int p = beg; p < end; p++) {
        int tn = (p + 1 < end) ? __ldg(&g_perm_s[p + 1]) : t;  // prefetch next idx
        int o = __ldg(&o_idx[t]);
        float lv = (lane < 16) ? __ldg(&g_lat2[(size_t)t * 16 + lane]) : 0.f;
        float hv = g_h[o * 32 + lane];
#pragma unroll
        for (int k = 1; k < 16; k++)
            acc[k] += __shfl_sync(0xffffffffu, lv, k) * hv;
        t = tn;
    }
    float* st = stage[wid];
#pragma unroll
    for (int k = 1; k < 16; k++) st[k * 32 + lane] = acc[k];
    __syncwarp();
#pragma unroll
    for (int it = 0; it < 4; it++) {
        int idx = it * 32 + lane;        // 0..127 over 16 rows x 8 float4
        if (idx >= 8) {                  // skip k=0 (handled by k_h2k0)
            int k = idx >> 3, q = idx & 7;
            float4 v = ((float4*)st)[idx];
            int j = s * k;
            red4(&((float4*)g_h2)[(size_t)j * 8 + q], v);
        }
    }
}

// ------------------- einsum + bias2: out, 2 nodes / thread ----------------
__global__ void __launch_bounds__(256)
k_out(const float* __restrict__ w2, const float* __restrict__ bias2,
      float* __restrict__ out) {
    extern __shared__ __align__(16) float sw2[];   // 16*32*32 floats = 64 KB
    for (int i = threadIdx.x; i < 16 * 32 * 32; i += 256) sw2[i] = w2[i];
    __syncthreads();
    int n0 = blockIdx.x * 256 + threadIdx.x;       // 0..24999
    if (n0 >= Nn / 2) return;
    int n1 = n0 + Nn / 2;
    ULL accA[16], accB[16];
#pragma unroll
    for (int c2 = 0; c2 < 16; c2++) {
        accA[c2] = ((const ULL*)bias2)[c2];
        accB[c2] = accA[c2];
    }
#pragma unroll 1
    for (int r = 0; r < 16; r++) {
        int jA = r * Nn + n0;
        int jB = jA + Nn / 2;
        float ra = g_rowsum[jA], rb = g_rowsum[jB];
        float invA = (ra > 0.f) ? __frcp_rn(ra) : 0.f;
        float invB = (rb > 0.f) ? __frcp_rn(rb) : 0.f;
        const float4* hA = (const float4*)&g_h2[(size_t)jA * 32];
        const float4* hB = (const float4*)&g_h2[(size_t)jB * 32];
#pragma unroll
        for (int e4 = 0; e4 < 8; e4++) {
            float4 va = hA[e4];
            float4 vb = hB[e4];
            float xa[4] = { va.x * invA, va.y * invA, va.z * invA, va.w * invA };
            float xb[4] = { vb.x * invB, vb.y * invB, vb.z * invB, vb.w * invB };
#pragma unroll
            for (int u = 0; u < 4; u++) {
                int e = e4 * 4 + u;
                ULL sa = splat2(xa[u]);
                ULL sb = splat2(xb[u]);
                const float4* wr4 = (const float4*)&sw2[(r * 32 + e) * 32];
#pragma unroll
                for (int c4 = 0; c4 < 8; c4++) {
                    F4U w; w.f = wr4[c4];
                    accA[2 * c4]     = ffma2(sa, w.u[0], accA[2 * c4]);
                    accA[2 * c4 + 1] = ffma2(sa, w.u[1], accA[2 * c4 + 1]);
                    accB[2 * c4]     = ffma2(sb, w.u[0], accB[2 * c4]);
                    accB[2 * c4 + 1] = ffma2(sb, w.u[1], accB[2 * c4 + 1]);
                }
            }
        }
    }
    ULL* opA = (ULL*)(out + (size_t)n0 * 32);
    ULL* opB = (ULL*)(out + (size_t)n1 * 32);
#pragma unroll
    for (int c2 = 0; c2 < 16; c2++) { opA[c2] = accA[c2]; opB[c2] = accB[c2]; }
}

// ------------------------- launch -----------------------------------------
extern "C" void kernel_launch(void* const* d_in, const int* in_sizes, int n_in,
                              void* d_out, int out_size) {
    const int*   s_idx = (const int*)d_in[0];
    const int*   o_idx = (const int*)d_in[1];
    const float* nhots = (const float*)d_in[2];
    const float* W1a   = (const float*)d_in[3];
    const float* b1a   = (const float*)d_in[4];
    const float* W1b   = (const float*)d_in[5];
    const float* b1b   = (const float*)d_in[6];
    const float* W2a   = (const float*)d_in[7];
    const float* b2a   = (const float*)d_in[8];
    const float* W2b   = (const float*)d_in[9];
    const float* b2b   = (const float*)d_in[10];
    const float* w1    = (const float*)d_in[11];
    const float* w2    = (const float*)d_in[12];
    const float* bias1 = (const float*)d_in[13];
    const float* bias2 = (const float*)d_in[14];
    float* out = (float*)d_out;

    static float* lat1p = nullptr;
    static float* lat2p = nullptr;
    static float* colp = nullptr;
    static float* rowp = nullptr;
    if (!lat1p) {
        cudaGetSymbolAddress((void**)&lat1p, g_lat1);
        cudaGetSymbolAddress((void**)&lat2p, g_lat2);
        cudaGetSymbolAddress((void**)&colp, g_colsum);
        cudaGetSymbolAddress((void**)&rowp, g_rowsum);
        cudaFuncSetAttribute(k_mlp, cudaFuncAttributeMaxDynamicSharedMemorySize,
                             SM_FLOATS * (int)sizeof(float));
        cudaFuncSetAttribute(k_out, cudaFuncAttributeMaxDynamicSharedMemorySize,
                             16 * 32 * 32 * (int)sizeof(float));
    }

    int mlp_blocks = (NTt + 127) / 128;
    size_t mlp_smem = SM_FLOATS * sizeof(float);

    k_init<<<2048, 256>>>();                                   // 0
    k_deg<<<(NTt + 255) / 256, 256>>>(s_idx, o_idx);           // 1
    k_alloc<<<(Nn + 255) / 256, 256>>>();                      // 2
    k_mlp<<<mlp_blocks, 256, mlp_smem>>>(s_idx, o_idx, nhots,  // 3 <- ncu slot
                                         W1a, b1a, W1b, b1b,
                                         W2a, b2a, W2b, b2b,
                                         lat1p, lat2p, colp, rowp);
    k_scatter<<<(NTt + 255) / 256, 256>>>(s_idx, o_idx);       // 4
    k_spmm1<<<(Nn * 32 + 255) / 256, 256>>>(s_idx, w1);        // 5
    k_relu<<<(Nn * Ee + 255) / 256, 256>>>(bias1);             // 6
    k_h2k0<<<512, 256>>>(o_idx);                               // 7
    k_spmm2<<<(Nn + 7) / 8, 256>>>(o_idx);                     // 8
    k_out<<<(Nn / 2 + 255) / 256, 256, 16 * 32 * 32 * (int)sizeof(float)>>>(w2, bias2, out); // 9
}